// round 12
// baseline (speedup 1.0000x reference)
#include <cuda_runtime.h>
#include <cuda_bf16.h>
#include <cstdint>
#include <math.h>

#define T_TOK   8192
#define H_DIM   1024
#define F_DIM   4096
#define E_NUM   8
#define A_NUM   (2 * T_TOK)

// ---------------- scratch (total static: 416MB + small) ----------------------
__device__ int   d_counts[E_NUM];
__device__ int   d_cursor[E_NUM];
__device__ int   d_off[E_NUM];
__device__ int   d_eidx[A_NUM];
__device__ float d_wt[A_NUM];
__device__ int   d_tok[A_NUM];
__device__ float d_swt[A_NUM];   // weight per slot

// packed bf16x2 hi/lo planes: word(kp, n) holds (k=2kp, k=2kp+1)
__device__ __align__(256) uint32_t d_xh[(size_t)T_TOK * (H_DIM / 2)];   // 16MB
__device__ __align__(256) uint32_t d_xl[(size_t)T_TOK * (H_DIM / 2)];   // 16MB
__device__ __align__(256) uint32_t d_w1h[(size_t)E_NUM * (H_DIM / 2) * F_DIM]; // 64MB
__device__ __align__(256) uint32_t d_w1l[(size_t)E_NUM * (H_DIM / 2) * F_DIM]; // 64MB
__device__ __align__(256) uint32_t d_hh[(size_t)A_NUM * (F_DIM / 2)];   // 128MB
__device__ __align__(256) uint32_t d_hl[(size_t)A_NUM * (F_DIM / 2)];   // 128MB

// ---------------- PTX --------------------------------------------------------
__device__ __forceinline__ void mma16816(float* c, const uint32_t* a, uint32_t b0, uint32_t b1) {
    asm volatile("mma.sync.aligned.m16n8k16.row.col.f32.bf16.bf16.f32 "
                 "{%0,%1,%2,%3}, {%4,%5,%6,%7}, {%8,%9}, {%0,%1,%2,%3};"
                 : "+f"(c[0]), "+f"(c[1]), "+f"(c[2]), "+f"(c[3])
                 : "r"(a[0]), "r"(a[1]), "r"(a[2]), "r"(a[3]), "r"(b0), "r"(b1));
}
__device__ __forceinline__ void split2(float x0, float x1, uint32_t& hi, uint32_t& lo) {
    uint32_t h;
    asm("cvt.rn.bf16x2.f32 %0, %1, %2;" : "=r"(h) : "f"(x1), "f"(x0));
    float f0 = __uint_as_float(h << 16);
    float f1 = __uint_as_float(h & 0xFFFF0000u);
    float r0 = x0 - f0;
    float r1 = x1 - f1;
    uint32_t l;
    asm("cvt.rn.bf16x2.f32 %0, %1, %2;" : "=r"(l) : "f"(r1), "f"(r0));
    hi = h; lo = l;
}

// ---------------- small kernels ----------------------------------------------
__global__ void init_kernel() {
    int i = threadIdx.x;
    if (i < E_NUM) { d_counts[i] = 0; d_cursor[i] = 0; }
}

__global__ void router_kernel(const float* __restrict__ x,
                              const float* __restrict__ rw,
                              const float* __restrict__ rb) {
    int warp = (blockIdx.x * blockDim.x + threadIdx.x) >> 5;
    int lane = threadIdx.x & 31;
    if (warp >= T_TOK) return;
    const float* xr = x + (size_t)warp * H_DIM;
    float acc[E_NUM];
#pragma unroll
    for (int e = 0; e < E_NUM; e++) acc[e] = 0.f;
    for (int k = lane; k < H_DIM; k += 32) {
        float xv = xr[k];
        const float* r = rw + (size_t)k * E_NUM;
#pragma unroll
        for (int e = 0; e < E_NUM; e++) acc[e] += xv * r[e];
    }
#pragma unroll
    for (int off = 16; off; off >>= 1)
#pragma unroll
        for (int e = 0; e < E_NUM; e++)
            acc[e] += __shfl_down_sync(0xffffffffu, acc[e], off);
    if (lane == 0) {
        float l[E_NUM];
#pragma unroll
        for (int e = 0; e < E_NUM; e++) l[e] = acc[e] + rb[e];
        int i0 = 0;
#pragma unroll
        for (int e = 1; e < E_NUM; e++) if (l[e] > l[i0]) i0 = e;
        int i1 = -1;
#pragma unroll
        for (int e = 0; e < E_NUM; e++)
            if (e != i0 && (i1 < 0 || l[e] > l[i1])) i1 = e;
        float m  = l[i0];
        float p1 = __expf(l[i1] - m);
        float s  = 1.f + p1;
        d_eidx[2 * warp + 0] = i0;  d_wt[2 * warp + 0] = 1.f / s;
        d_eidx[2 * warp + 1] = i1;  d_wt[2 * warp + 1] = p1 / s;
        atomicAdd(&d_counts[i0], 1);
        atomicAdd(&d_counts[i1], 1);
    }
}

__global__ void offsets_kernel() {
    if (threadIdx.x == 0) {
        int acc = 0;
        for (int e = 0; e < E_NUM; e++) { d_off[e] = acc; acc += d_counts[e]; }
    }
}

__global__ void scatter_kernel() {
    int t = blockIdx.x * blockDim.x + threadIdx.x;
    if (t >= T_TOK) return;
#pragma unroll
    for (int j = 0; j < 2; j++) {
        int e   = d_eidx[2 * t + j];
        int pos = d_off[e] + atomicAdd(&d_cursor[e], 1);
        d_tok[pos] = t;
        d_swt[pos] = d_wt[2 * t + j];
    }
}

__global__ void zero_out_kernel(float* __restrict__ out) {
    int idx = blockIdx.x * blockDim.x + threadIdx.x;
    if (idx < T_TOK * (H_DIM / 4)) ((float4*)out)[idx] = make_float4(0.f, 0.f, 0.f, 0.f);
}

// ---------------- prepass: split to packed planes ----------------------------
__global__ void convert_x_kernel(const float* __restrict__ x) {
    int idx = blockIdx.x * blockDim.x + threadIdx.x;
    if (idx >= T_TOK * (H_DIM / 2)) return;
    float2 v = ((const float2*)x)[idx];
    split2(v.x, v.y, d_xh[idx], d_xl[idx]);
}

// w1: [E][H][F] -> planes [E][H/2][F]
__global__ void convert_w1_kernel(const float* __restrict__ W) {
    int idx = blockIdx.x * blockDim.x + threadIdx.x;
    if (idx >= E_NUM * (H_DIM / 2) * F_DIM) return;
    int n    = idx % F_DIM;
    int ekp  = idx / F_DIM;
    size_t s = (size_t)ekp * 2 * F_DIM + n;
    split2(W[s], W[s + F_DIM], d_w1h[idx], d_w1l[idx]);
}

// ---------------- grouped GEMM: 256x128 block, 64x64 warp --------------------
#define A_SLAB   520
#define A_L_OFF  (4 * A_SLAB)
#define B_H_OFF  (8 * A_SLAB)
#define B_SLAB   264
#define B_L_OFF  (B_H_OFF + 4 * B_SLAB)
#define SMW_TOT  (B_L_OFF + 4 * B_SLAB)

__device__ __forceinline__ float gelu_tanh(float v) {
    float c = 0.7978845608028654f * (v + 0.044715f * v * v * v);
    return 0.5f * v * (1.f + tanhf(c));
}

template <bool G1>
__global__ __launch_bounds__(256, 1) void moe_gemm(const float* __restrict__ W2,
                                                   const float* __restrict__ bias,
                                                   float* __restrict__ out) {
    constexpr int K_TOT = G1 ? H_DIM : F_DIM;
    constexpr int N_TOT = G1 ? F_DIM : H_DIM;
    constexpr int KW    = K_TOT / 2;
    constexpr int NCH   = K_TOT / 16;

    int e   = blockIdx.z;
    int cnt = d_counts[e];
    int m0  = blockIdx.y * 256;
    if (m0 >= cnt) return;
    int off = d_off[e];
    int n0  = blockIdx.x * 128;

    __shared__ uint32_t smw[SMW_TOT];

    int tid  = threadIdx.x;
    int lane = tid & 31;
    int w    = tid >> 5;
    int wm   = (w >> 1) * 64;
    int wn   = (w & 1) * 64;
    int gid  = lane >> 2;
    int tg   = lane & 3;

    // A plane row (both GEMMs copy-fed)
    int ar = tid;
    int arow_ok = (m0 + ar < cnt);
    size_t arow;
    const uint32_t* Ah;
    const uint32_t* Al;
    if (G1) {
        Ah = d_xh; Al = d_xl;
        arow = (size_t)d_tok[off + (arow_ok ? m0 + ar : 0)] * KW;
    } else {
        Ah = d_hh; Al = d_hl;
        arow = (size_t)(off + (arow_ok ? m0 + ar : 0)) * KW;
    }
    const uint32_t* Bh = d_w1h + (size_t)e * KW * N_TOT;   // G1 only
    const uint32_t* Bl = d_w1l + (size_t)e * KW * N_TOT;
    const float*    B2 = W2 + (size_t)e * (size_t)K_TOT * N_TOT;  // G2 only

    int tg_s = tid >> 6;
    int l64  = tid & 63;

    float acc[4][8][4];
#pragma unroll
    for (int mt = 0; mt < 4; mt++)
#pragma unroll
        for (int nt = 0; nt < 8; nt++)
#pragma unroll
            for (int j = 0; j < 4; j++) acc[mt][nt][j] = 0.f;

    // prefetch chunk 0
    uint4 pah[2], pal[2];
    uint32_t pbh[4], pbl[4];
    float pb[8];
    pah[0] = *(const uint4*)(Ah + arow);     pah[1] = *(const uint4*)(Ah + arow + 4);
    pal[0] = *(const uint4*)(Al + arow);     pal[1] = *(const uint4*)(Al + arow + 4);
    if (G1) {
#pragma unroll
        for (int j = 0; j < 2; j++) {
            pbh[j * 2 + 0] = Bh[(size_t)tg_s * N_TOT + n0 + l64 + 64 * j];
            pbh[j * 2 + 1] = Bh[(size_t)(tg_s + 4) * N_TOT + n0 + l64 + 64 * j];
            pbl[j * 2 + 0] = Bl[(size_t)tg_s * N_TOT + n0 + l64 + 64 * j];
            pbl[j * 2 + 1] = Bl[(size_t)(tg_s + 4) * N_TOT + n0 + l64 + 64 * j];
        }
    } else {
        int rr[4] = {2 * tg_s, 2 * tg_s + 1, 2 * tg_s + 8, 2 * tg_s + 9};
#pragma unroll
        for (int ri = 0; ri < 4; ri++)
#pragma unroll
            for (int j = 0; j < 2; j++)
                pb[ri * 2 + j] = B2[(size_t)rr[ri] * N_TOT + n0 + l64 + 64 * j];
    }

    for (int ch = 0; ch < NCH; ch++) {
        // ---- stage ----
        {
            uint32_t uh[8] = {pah[0].x, pah[0].y, pah[0].z, pah[0].w,
                              pah[1].x, pah[1].y, pah[1].z, pah[1].w};
            uint32_t ul[8] = {pal[0].x, pal[0].y, pal[0].z, pal[0].w,
                              pal[1].x, pal[1].y, pal[1].z, pal[1].w};
#pragma unroll
            for (int kq = 0; kq < 4; kq++) {
                *(uint2*)&smw[kq * A_SLAB + 2 * ar]           = make_uint2(uh[kq], uh[kq + 4]);
                *(uint2*)&smw[A_L_OFF + kq * A_SLAB + 2 * ar] = make_uint2(ul[kq], ul[kq + 4]);
            }
            if (G1) {
#pragma unroll
                for (int j = 0; j < 2; j++) {
                    int n = l64 + 64 * j;
                    *(uint2*)&smw[B_H_OFF + tg_s * B_SLAB + 2 * n] = make_uint2(pbh[j * 2 + 0], pbh[j * 2 + 1]);
                    *(uint2*)&smw[B_L_OFF + tg_s * B_SLAB + 2 * n] = make_uint2(pbl[j * 2 + 0], pbl[j * 2 + 1]);
                }
            } else {
#pragma unroll
                for (int j = 0; j < 2; j++) {
                    uint32_t h0, l0, h1, l1;
                    split2(pb[0 + j], pb[2 + j], h0, l0);
                    split2(pb[4 + j], pb[6 + j], h1, l1);
                    int n = l64 + 64 * j;
                    *(uint2*)&smw[B_H_OFF + tg_s * B_SLAB + 2 * n] = make_uint2(h0, h1);
                    *(uint2*)&smw[B_L_OFF + tg_s * B_SLAB + 2 * n] = make_uint2(l0, l1);
                }
            }
        }
        __syncthreads();

        // ---- prefetch next chunk ----
        if (ch + 1 < NCH) {
            int kb = (ch + 1) * 8;
            pah[0] = *(const uint4*)(Ah + arow + kb);     pah[1] = *(const uint4*)(Ah + arow + kb + 4);
            pal[0] = *(const uint4*)(Al + arow + kb);     pal[1] = *(const uint4*)(Al + arow + kb + 4);
            if (G1) {
#pragma unroll
                for (int j = 0; j < 2; j++) {
                    pbh[j * 2 + 0] = Bh[(size_t)(kb + tg_s) * N_TOT + n0 + l64 + 64 * j];
                    pbh[j * 2 + 1] = Bh[(size_t)(kb + tg_s + 4) * N_TOT + n0 + l64 + 64 * j];
                    pbl[j * 2 + 0] = Bl[(size_t)(kb + tg_s) * N_TOT + n0 + l64 + 64 * j];
                    pbl[j * 2 + 1] = Bl[(size_t)(kb + tg_s + 4) * N_TOT + n0 + l64 + 64 * j];
                }
            } else {
                int k1 = (ch + 1) * 16;
                int rr[4] = {k1 + 2 * tg_s, k1 + 2 * tg_s + 1, k1 + 2 * tg_s + 8, k1 + 2 * tg_s + 9};
#pragma unroll
                for (int ri = 0; ri < 4; ri++)
#pragma unroll
                    for (int j = 0; j < 2; j++)
                        pb[ri * 2 + j] = B2[(size_t)rr[ri] * N_TOT + n0 + l64 + 64 * j];
            }
        }

        // ---- compute ----
        uint32_t bh[8][2], bl[8][2];
#pragma unroll
        for (int nt = 0; nt < 8; nt++) {
            int cb = wn + nt * 8 + gid;
            uint2 H = *(uint2*)&smw[B_H_OFF + tg * B_SLAB + 2 * cb];
            uint2 L = *(uint2*)&smw[B_L_OFF + tg * B_SLAB + 2 * cb];
            bh[nt][0] = H.x; bh[nt][1] = H.y;
            bl[nt][0] = L.x; bl[nt][1] = L.y;
        }
#pragma unroll
        for (int mt = 0; mt < 4; mt++) {
            int ca = wm + mt * 16 + gid;
            uint2 H0 = *(uint2*)&smw[tg * A_SLAB + 2 * ca];
            uint2 H1 = *(uint2*)&smw[tg * A_SLAB + 2 * (ca + 8)];
            uint2 L0 = *(uint2*)&smw[A_L_OFF + tg * A_SLAB + 2 * ca];
            uint2 L1 = *(uint2*)&smw[A_L_OFF + tg * A_SLAB + 2 * (ca + 8)];
            uint32_t ah[4] = {H0.x, H1.x, H0.y, H1.y};
            uint32_t al[4] = {L0.x, L1.x, L0.y, L1.y};
#pragma unroll
            for (int nt = 0; nt < 8; nt++) {
                mma16816(acc[mt][nt], ah, bh[nt][0], bh[nt][1]);
                mma16816(acc[mt][nt], ah, bl[nt][0], bl[nt][1]);
                mma16816(acc[mt][nt], al, bh[nt][0], bh[nt][1]);
            }
        }
        __syncthreads();
    }

    // ---- epilogue ----
    const float* bp = bias + (size_t)e * N_TOT + n0;
#pragma unroll
    for (int mt = 0; mt < 4; mt++) {
#pragma unroll
        for (int half = 0; half < 2; half++) {
            int m = m0 + wm + mt * 16 + gid + half * 8;
            if (m >= cnt) continue;
            int slot = off + m;
#pragma unroll
            for (int nt = 0; nt < 8; nt++) {
                int col = wn + nt * 8 + tg * 2;
                float v0 = acc[mt][nt][half * 2 + 0] + bp[col];
                float v1 = acc[mt][nt][half * 2 + 1] + bp[col + 1];
                if (G1) {
                    float g0 = gelu_tanh(v0), g1 = gelu_tanh(v1);
                    uint32_t hw, lw;
                    split2(g0, g1, hw, lw);
                    size_t wi = (size_t)slot * (F_DIM / 2) + ((n0 + col) >> 1);
                    d_hh[wi] = hw;
                    d_hl[wi] = lw;
                } else {
                    int   t  = d_tok[slot];
                    float wt = d_swt[slot];
                    float* op = out + (size_t)t * H_DIM + n0 + col;
                    atomicAdd(op,     wt * v0);
                    atomicAdd(op + 1, wt * v1);
                }
            }
        }
    }
}

// ---------------- launch -----------------------------------------------------
extern "C" void kernel_launch(void* const* d_in, const int* in_sizes, int n_in,
                              void* d_out, int out_size) {
    const float* x  = (const float*)d_in[0];
    const float* rw = (const float*)d_in[1];
    const float* rb = (const float*)d_in[2];
    const float* w1 = (const float*)d_in[3];
    const float* b1 = (const float*)d_in[4];
    const float* w2 = (const float*)d_in[5];
    const float* b2 = (const float*)d_in[6];
    float* out = (float*)d_out;

    init_kernel<<<1, 32>>>();
    router_kernel<<<T_TOK / 4, 128>>>(x, rw, rb);
    offsets_kernel<<<1, 32>>>();
    scatter_kernel<<<(T_TOK + 255) / 256, 256>>>();

    convert_x_kernel<<<(T_TOK * (H_DIM / 2) + 255) / 256, 256>>>(x);
    convert_w1_kernel<<<(E_NUM * (H_DIM / 2) * F_DIM + 255) / 256, 256>>>(w1);
    zero_out_kernel<<<(T_TOK * (H_DIM / 4) + 255) / 256, 256>>>(out);

    dim3 g1(F_DIM / 128, T_TOK / 256, E_NUM);   // (32, 32, 8)
    moe_gemm<true><<<g1, 256>>>(w2, b1, out);
    dim3 g2(H_DIM / 128, T_TOK / 256, E_NUM);   // (8, 32, 8)
    moe_gemm<false><<<g2, 256>>>(w2, b2, out);
}